// round 10
// baseline (speedup 1.0000x reference)
#include <cuda_runtime.h>
#include <cuda_bf16.h>
#include <math.h>
#include <stdint.h>

// Problem dimensions (fixed by the dataset)
#define SS 512   // timesteps
#define BB 128   // batch
#define DD 256   // input dim
#define HH 512   // hidden
#define GG 2048  // 4*H (gate-interleaved: col n = j*4 + gate)
#define BH (BB*HH)

// Device scratch (no runtime allocation allowed)
__device__ float g_bias[GG];                 // interleaved bias [2048]
__device__ __nv_bfloat16 g_UThi[GG*HH];      // U'^T hi  [2048 n][512 k] bf16
__device__ __nv_bfloat16 g_UTlo[GG*HH];      // U'^T lo
__device__ __nv_bfloat16 g_WThi[GG*DD];      // W'^T hi  [2048 n][256 k] bf16
__device__ __nv_bfloat16 g_WTlo[GG*DD];      // W'^T lo
__device__ __nv_bfloat16 g_xhi[(size_t)SS*BB*DD];  // x hi  [65536 m][256 k] bf16
__device__ __nv_bfloat16 g_xlo[(size_t)SS*BB*DD];  // x lo
__device__ __nv_bfloat16 g_hBhi[2*BB*HH];    // double-buffered h hi [2][128 b][512 k]
__device__ __nv_bfloat16 g_hBlo[2*BB*HH];    // double-buffered h lo
__device__ float g_mdhp[BH];                 // tanh(alpha@A - (beta*ts)@B + theta@C)
__device__ float g_c[BH];                    // final cell state (for finalize)
__device__ float g_xw[(size_t)SS*BB*GG];     // precomputed x@W' + b  (512 MB)
__device__ unsigned g_ctr4[4];               // per-rowgroup barrier counters

// ---------------------------------------------------------------------------
// helpers
// ---------------------------------------------------------------------------
__device__ __forceinline__ void mma_bf16(float* c, uint32_t a0, uint32_t a1,
                                         uint32_t a2, uint32_t a3,
                                         uint32_t b0, uint32_t b1) {
    asm volatile("mma.sync.aligned.m16n8k16.row.col.f32.bf16.bf16.f32 "
        "{%0,%1,%2,%3}, {%4,%5,%6,%7}, {%8,%9}, {%0,%1,%2,%3};"
        : "+f"(c[0]), "+f"(c[1]), "+f"(c[2]), "+f"(c[3])
        : "r"(a0), "r"(a1), "r"(a2), "r"(a3), "r"(b0), "r"(b1));
}

// ---------------------------------------------------------------------------
// Build bf16-split U'^T, W'^T (both [n][k], n gate-interleaved), and bias.
// ---------------------------------------------------------------------------
__global__ void prep_weights(const float* __restrict__ Wi, const float* __restrict__ Ui, const float* __restrict__ bi,
                             const float* __restrict__ Wf, const float* __restrict__ Uf, const float* __restrict__ bf,
                             const float* __restrict__ Wc, const float* __restrict__ Uc, const float* __restrict__ bc,
                             const float* __restrict__ Wo, const float* __restrict__ Uo, const float* __restrict__ bo)
{
    int idx = blockIdx.x * blockDim.x + threadIdx.x;
    int stride = gridDim.x * blockDim.x;
    for (int i = idx; i < HH * GG; i += stride) {
        {   // U'^T bf16 hi/lo: i = n*512 + k
            int n = i >> 9, k = i & 511;
            int j = n >> 2, g = n & 3;
            const float* U = (g == 0) ? Ui : (g == 1) ? Uf : (g == 2) ? Uc : Uo;
            float u = U[k * HH + j];
            __nv_bfloat16 hi = __float2bfloat16(u);
            g_UThi[i] = hi;
            g_UTlo[i] = __float2bfloat16(u - __bfloat162float(hi));
        }
        if (i < GG * DD) {   // W'^T bf16 hi/lo: i = n*256 + k
            int n = i >> 8, k = i & 255;
            int j = n >> 2, g = n & 3;
            const float* W = (g == 0) ? Wi : (g == 1) ? Wf : (g == 2) ? Wc : Wo;
            float w = W[k * HH + j];
            __nv_bfloat16 hi = __float2bfloat16(w);
            g_WThi[i] = hi;
            g_WTlo[i] = __float2bfloat16(w - __bfloat162float(hi));
        }
        if (i < GG) {
            int j = i >> 2, g = i & 3;
            const float* bptr = (g == 0) ? bi : (g == 1) ? bf : (g == 2) ? bc : bo;
            g_bias[i] = bptr[j];
        }
    }
}

// split x into bf16 hi/lo (16.7M elements, 4 per thread)
__global__ void xsplit(const float* __restrict__ x)
{
    size_t i = (size_t)blockIdx.x * blockDim.x + threadIdx.x;   // float4 index
    float4 v = *((const float4*)x + i);
    __nv_bfloat16 h0 = __float2bfloat16(v.x);
    __nv_bfloat16 h1 = __float2bfloat16(v.y);
    __nv_bfloat16 h2 = __float2bfloat16(v.z);
    __nv_bfloat16 h3 = __float2bfloat16(v.w);
    __nv_bfloat16 l0 = __float2bfloat16(v.x - __bfloat162float(h0));
    __nv_bfloat16 l1 = __float2bfloat16(v.y - __bfloat162float(h1));
    __nv_bfloat16 l2 = __float2bfloat16(v.z - __bfloat162float(h2));
    __nv_bfloat16 l3 = __float2bfloat16(v.w - __bfloat162float(h3));
    ushort4 ph = make_ushort4(__bfloat16_as_ushort(h0), __bfloat16_as_ushort(h1),
                              __bfloat16_as_ushort(h2), __bfloat16_as_ushort(h3));
    ushort4 pl = make_ushort4(__bfloat16_as_ushort(l0), __bfloat16_as_ushort(l1),
                              __bfloat16_as_ushort(l2), __bfloat16_as_ushort(l3));
    *((ushort4*)g_xhi + i) = ph;
    *((ushort4*)g_xlo + i) = pl;
}

// ---------------------------------------------------------------------------
// mdhp = tanh(alpha @ A - (beta*tspan) @ B + theta @ C)   [B,H]
// ---------------------------------------------------------------------------
__global__ void mdhp_kernel(const float* __restrict__ alpha, const float* __restrict__ beta,
                            const float* __restrict__ theta, const float* __restrict__ tspan,
                            const float* __restrict__ A, const float* __restrict__ Bm,
                            const float* __restrict__ C)
{
    int b = blockIdx.x;
    int j = threadIdx.x;   // 0..511
    __shared__ float sa[256], sb[256], st[16];
    float ts = tspan[b];
    if (j < 256) {
        sa[j] = alpha[b * 256 + j];
        sb[j] = beta[b * 256 + j] * ts;
    }
    if (j < 16) st[j] = theta[b * 16 + j];
    __syncthreads();
    float acc = 0.f;
    #pragma unroll 4
    for (int k = 0; k < 256; k++)
        acc += sa[k] * A[k * 512 + j] - sb[k] * Bm[k * 512 + j];
    #pragma unroll
    for (int k = 0; k < 16; k++)
        acc += st[k] * C[k * 512 + j];
    g_mdhp[b * 512 + j] = tanhf(acc);
}

// zero barrier counters + bf16-split h0 into g_hB buffer 0
__global__ void prep_state(const float* __restrict__ h0)
{
    int i = blockIdx.x * blockDim.x + threadIdx.x;
    if (i < 4) g_ctr4[i] = 0u;
    if (i < BB * HH) {
        float v = h0[i];                       // i = b*512 + k
        __nv_bfloat16 hi = __float2bfloat16(v);
        g_hBhi[i] = hi;
        g_hBlo[i] = __float2bfloat16(v - __bfloat162float(hi));
    }
}

// ---------------------------------------------------------------------------
// xW GEMM on mma.sync bf16 (2-way split, 3-term product):
//   g_xw[65536, 2048] = x[65536, 256] @ W'[256, 2048] + bias
// Block: 128x128 C tile, 512 threads = 16 warps (4 M x 4 N), warp tile 32x32.
// K in 4 chunks of 64; register prefetch of next chunk overlaps the mma loop.
// smem rows padded to 36 words (conflict-free 4r+tq bank map).
// ---------------------------------------------------------------------------
#define ROWX 36   // uint32 words per padded row (32 data words = 64 bf16)
__global__ __launch_bounds__(512, 1) void xw_mma()
{
    extern __shared__ __align__(16) uint32_t xs[];
    uint32_t* a_hi = xs;                    // [128][36]
    uint32_t* a_lo = xs + 128 * ROWX;
    uint32_t* b_hi = xs + 2 * 128 * ROWX;
    uint32_t* b_lo = xs + 3 * 128 * ROWX;

    const int tid  = threadIdx.x;
    const int lane = tid & 31;
    const int wid  = tid >> 5;              // 0..15
    const int mbase = (wid & 3) * 32;       // 0,32,64,96
    const int nbase = (wid >> 2) * 32;      // 0,32,64,96
    const int r  = lane >> 2;               // 0..7
    const int tq = lane & 3;                // 0..3
    const int n0 = blockIdx.x * 128;
    const int m0 = blockIdx.y * 128;

    // loader mapping: 2 uint4 per array per thread per chunk
    const int lrow0 = tid >> 3;             // 0..63
    const int lc4   = tid & 7;              // 0..7

    float c[2][4][4];
    #pragma unroll
    for (int f = 0; f < 2; f++)
        #pragma unroll
        for (int j = 0; j < 4; j++)
            #pragma unroll
            for (int q = 0; q < 4; q++) c[f][j][q] = 0.f;

    // prefetch chunk 0 into registers
    uint4 pah[2], pal[2], pbh[2], pbl[2];
    #pragma unroll
    for (int q = 0; q < 2; q++) {
        int row = lrow0 + q * 64;
        pah[q] = *((const uint4*)(g_xhi  + (size_t)(m0 + row) * DD) + lc4);
        pal[q] = *((const uint4*)(g_xlo  + (size_t)(m0 + row) * DD) + lc4);
        pbh[q] = *((const uint4*)(g_WThi + (size_t)(n0 + row) * DD) + lc4);
        pbl[q] = *((const uint4*)(g_WTlo + (size_t)(n0 + row) * DD) + lc4);
    }

    for (int kc = 0; kc < 4; kc++) {
        // stage prefetched regs -> smem
        #pragma unroll
        for (int q = 0; q < 2; q++) {
            int row = lrow0 + q * 64;
            *(uint4*)(a_hi + row * ROWX + lc4 * 4) = pah[q];
            *(uint4*)(a_lo + row * ROWX + lc4 * 4) = pal[q];
            *(uint4*)(b_hi + row * ROWX + lc4 * 4) = pbh[q];
            *(uint4*)(b_lo + row * ROWX + lc4 * 4) = pbl[q];
        }
        __syncthreads();

        // prefetch next chunk (overlaps mma below)
        if (kc < 3) {
            const int k1 = (kc + 1) * 64;
            #pragma unroll
            for (int q = 0; q < 2; q++) {
                int row = lrow0 + q * 64;
                pah[q] = *((const uint4*)(g_xhi  + (size_t)(m0 + row) * DD + k1) + lc4);
                pal[q] = *((const uint4*)(g_xlo  + (size_t)(m0 + row) * DD + k1) + lc4);
                pbh[q] = *((const uint4*)(g_WThi + (size_t)(n0 + row) * DD + k1) + lc4);
                pbl[q] = *((const uint4*)(g_WTlo + (size_t)(n0 + row) * DD + k1) + lc4);
            }
        }

        #pragma unroll
        for (int ks = 0; ks < 4; ks++) {
            const int kw = ks * 8 + tq;
            uint32_t ah[2][4], al[2][4];
            #pragma unroll
            for (int f = 0; f < 2; f++) {
                int ar0 = (mbase + f * 16 + r) * ROWX;
                int ar1 = (mbase + f * 16 + r + 8) * ROWX;
                ah[f][0] = a_hi[ar0 + kw]; ah[f][1] = a_hi[ar1 + kw];
                ah[f][2] = a_hi[ar0 + kw + 4]; ah[f][3] = a_hi[ar1 + kw + 4];
                al[f][0] = a_lo[ar0 + kw]; al[f][1] = a_lo[ar1 + kw];
                al[f][2] = a_lo[ar0 + kw + 4]; al[f][3] = a_lo[ar1 + kw + 4];
            }
            #pragma unroll
            for (int j = 0; j < 4; j++) {
                int nr = (nbase + j * 8 + r) * ROWX + kw;
                uint32_t bh0 = b_hi[nr], bh1 = b_hi[nr + 4];
                uint32_t bl0 = b_lo[nr], bl1 = b_lo[nr + 4];
                #pragma unroll
                for (int f = 0; f < 2; f++) {
                    mma_bf16(c[f][j], ah[f][0], ah[f][1], ah[f][2], ah[f][3], bh0, bh1);
                    mma_bf16(c[f][j], ah[f][0], ah[f][1], ah[f][2], ah[f][3], bl0, bl1);
                    mma_bf16(c[f][j], al[f][0], al[f][1], al[f][2], al[f][3], bh0, bh1);
                }
            }
        }
        __syncthreads();
    }

    // epilogue: c0(r,2tq) c1(r,2tq+1) c2(r+8,2tq) c3(r+8,2tq+1)
    #pragma unroll
    for (int f = 0; f < 2; f++) {
        int row0 = m0 + mbase + f * 16 + r;
        #pragma unroll
        for (int j = 0; j < 4; j++) {
            int col = n0 + nbase + j * 8 + 2 * tq;
            float2 bb = *(const float2*)&g_bias[col];
            float2 o0 = make_float2(c[f][j][0] + bb.x, c[f][j][1] + bb.y);
            float2 o1 = make_float2(c[f][j][2] + bb.x, c[f][j][3] + bb.y);
            *(float2*)&g_xw[(size_t)row0 * GG + col]       = o0;
            *(float2*)&g_xw[(size_t)(row0 + 8) * GG + col] = o1;
        }
    }
}

// ---------------------------------------------------------------------------
// Persistent LSTM recurrence on mma.sync bf16 (unchanged from round 8 — proven).
// ---------------------------------------------------------------------------
#define ROWW 260   // uint32 words per padded bf16 row (520 bf16; 256 data words)
__global__ __launch_bounds__(512) void lstm_persist(const float* __restrict__ c0,
                                                    float* __restrict__ out)
{
    extern __shared__ __align__(16) uint32_t smw[];
    uint32_t* u_hi = smw;                               // [64][260]
    uint32_t* u_lo = smw + 64 * ROWW;                   // [64][260]
    uint32_t* h_hi = smw + 2 * 64 * ROWW;               // [32][260]
    uint32_t* h_lo = smw + 2 * 64 * ROWW + 32 * ROWW;   // [32][260]
    float*    part = (float*)(smw + 2 * 64 * ROWW + 2 * 32 * ROWW); // [2][32][68]

    const int tid = threadIdx.x;
    const int bx  = blockIdx.x;            // 0..31 col block
    const int rg  = blockIdx.y;            // 0..3  row group
    const int n0  = bx * 64;               // interleaved gate-col base
    const int b0  = rg * 32;               // batch row base

    const int lane = tid & 31;
    const int wid  = tid >> 5;             // 0..15
    const int kseg  = wid >> 3;            // 0..1  K half
    const int ow    = wid & 7;             // 0..7  output warp
    const int mbase = (ow >> 2) * 16;      // 0 or 16
    const int nbase = (ow & 3) * 16;       // 0,16,32,48
    const int r  = lane >> 2;              // 0..7
    const int tq = lane & 3;               // 0..3

    const int pr = tid >> 4;               // 0..31
    const int pj = tid & 15;               // 0..15
    const int jglob = bx * 16 + pj;
    const int pidx = (b0 + pr) * HH + jglob;

    // ---- load persistent U'^T slice (bf16 hi/lo) ----
    #pragma unroll
    for (int q = 0; q < 8; q++) {
        int u = tid + q * 512;              // 0..4095
        int row = u >> 6;                   // 0..63
        int c4  = u & 63;
        uint4 vh = *((const uint4*)(g_UThi + (size_t)(n0 + row) * HH) + c4);
        uint4 vl = *((const uint4*)(g_UTlo + (size_t)(n0 + row) * HH) + c4);
        *(uint4*)(u_hi + row * ROWW + c4 * 4) = vh;
        *(uint4*)(u_lo + row * ROWW + c4 * 4) = vl;
    }

    float cr = c0[pidx];
    float mr = g_mdhp[pidx];
    __syncthreads();

    for (int t = 0; t < SS; t++) {
        const __nv_bfloat16* hbh = g_hBhi + (size_t)(t & 1) * (BB * HH);
        const __nv_bfloat16* hbl = g_hBlo + (size_t)(t & 1) * (BB * HH);
        #pragma unroll
        for (int q = 0; q < 4; q++) {
            int u = tid + q * 512;          // 0..2047
            int row = u >> 6;               // 0..31
            int c4  = u & 63;
            uint4 vh = __ldcg((const uint4*)(hbh + (size_t)(b0 + row) * HH) + c4);
            uint4 vl = __ldcg((const uint4*)(hbl + (size_t)(b0 + row) * HH) + c4);
            *(uint4*)(h_hi + row * ROWW + c4 * 4) = vh;
            *(uint4*)(h_lo + row * ROWW + c4 * 4) = vl;
        }
        float4 xw4 = *(const float4*)&g_xw[((size_t)t * BB + b0 + pr) * GG + n0 + pj * 4];
        __syncthreads();

        float c[2][4] = {};
        const int arow0 = (mbase + r) * ROWW;
        const int arow1 = (mbase + r + 8) * ROWW;
        #pragma unroll 4
        for (int ks = 0; ks < 16; ks++) {
            int kw = kseg * 128 + ks * 8 + tq;
            uint32_t ah0 = h_hi[arow0 + kw];
            uint32_t ah1 = h_hi[arow1 + kw];
            uint32_t ah2 = h_hi[arow0 + kw + 4];
            uint32_t ah3 = h_hi[arow1 + kw + 4];
            uint32_t al0 = h_lo[arow0 + kw];
            uint32_t al1 = h_lo[arow1 + kw];
            uint32_t al2 = h_lo[arow0 + kw + 4];
            uint32_t al3 = h_lo[arow1 + kw + 4];
            #pragma unroll
            for (int j = 0; j < 2; j++) {
                int nr = (nbase + j * 8 + r) * ROWW + kw;
                uint32_t bh0 = u_hi[nr], bh1 = u_hi[nr + 4];
                uint32_t bl0 = u_lo[nr], bl1 = u_lo[nr + 4];
                mma_bf16(c[j], ah0, ah1, ah2, ah3, bh0, bh1);
                mma_bf16(c[j], ah0, ah1, ah2, ah3, bl0, bl1);
                mma_bf16(c[j], al0, al1, al2, al3, bh0, bh1);
            }
        }

        #pragma unroll
        for (int j = 0; j < 2; j++) {
            float* p = part + kseg * (32 * 68) + (mbase + r) * 68 + nbase + j * 8 + 2 * tq;
            *(float2*)p            = make_float2(c[j][0], c[j][1]);
            *(float2*)(p + 8 * 68) = make_float2(c[j][2], c[j][3]);
        }
        __syncthreads();

        {
            float4 p0 = *(const float4*)&part[pr * 68 + pj * 4];
            float4 p1 = *(const float4*)&part[32 * 68 + pr * 68 + pj * 4];
            float gi = p0.x + p1.x + xw4.x;
            float gf = p0.y + p1.y + xw4.y;
            float gc = p0.z + p1.z + xw4.z;
            float go = p0.w + p1.w + xw4.w;
            float it_ = 1.f / (1.f + __expf(-gi));
            float ft  = 1.f / (1.f + __expf(-gf));
            float ch  = tanhf(gc);
            float ot  = 1.f / (1.f + __expf(-go));
            float cn  = mr * (ft * cr + it_ * ch);
            cr = cn;
            float hn = ot * tanhf(cn);
            out[(size_t)t * BH + pidx] = hn;
            size_t nb = (size_t)((t + 1) & 1) * (BB * HH);
            __nv_bfloat16 hb = __float2bfloat16(hn);
            g_hBhi[nb + pidx] = hb;
            g_hBlo[nb + pidx] = __float2bfloat16(hn - __bfloat162float(hb));
        }

        __syncthreads();
        if (tid == 0) {
            __threadfence();
            atomicAdd(&g_ctr4[rg], 1u);
            unsigned target = (unsigned)(t + 1) * 32u;
            while (*(volatile unsigned*)&g_ctr4[rg] < target) { }
            __threadfence();
        }
        __syncthreads();
    }

    g_c[pidx] = cr;
}

// copy h_T (== outputs[S-1]) and c_T into the output tail
__global__ void finalize(float* __restrict__ out)
{
    int i = blockIdx.x * blockDim.x + threadIdx.x;
    if (i < BH) {
        out[(size_t)SS * BH + i]      = out[(size_t)(SS - 1) * BH + i];
        out[(size_t)SS * BH + BH + i] = g_c[i];
    }
}

// ---------------------------------------------------------------------------
extern "C" void kernel_launch(void* const* d_in, const int* in_sizes, int n_in,
                              void* d_out, int out_size)
{
    const float* x     = (const float*)d_in[0];
    const float* h0    = (const float*)d_in[1];
    const float* c0    = (const float*)d_in[2];
    const float* alpha = (const float*)d_in[3];
    const float* beta  = (const float*)d_in[4];
    const float* theta = (const float*)d_in[5];
    const float* tspan = (const float*)d_in[6];
    const float* A     = (const float*)d_in[7];
    const float* Bm    = (const float*)d_in[8];
    const float* C     = (const float*)d_in[9];
    const float* Wi = (const float*)d_in[10];
    const float* Ui = (const float*)d_in[11];
    const float* bi = (const float*)d_in[12];
    const float* Wf = (const float*)d_in[13];
    const float* Uf = (const float*)d_in[14];
    const float* bf = (const float*)d_in[15];
    const float* Wc = (const float*)d_in[16];
    const float* Uc = (const float*)d_in[17];
    const float* bc = (const float*)d_in[18];
    const float* Wo = (const float*)d_in[19];
    const float* Uo = (const float*)d_in[20];
    const float* bo = (const float*)d_in[21];
    float* out = (float*)d_out;

    const int SMEM  = (2 * 64 * ROWW + 2 * 32 * ROWW + 2 * 32 * 68) * 4;  // 217088 B
    const int XSMEM = 4 * 128 * ROWX * 4;                                  // 73728 B
    cudaFuncSetAttribute(lstm_persist, cudaFuncAttributeMaxDynamicSharedMemorySize, SMEM);
    cudaFuncSetAttribute(xw_mma, cudaFuncAttributeMaxDynamicSharedMemorySize, XSMEM);

    prep_weights<<<1024, 256>>>(Wi, Ui, bi, Wf, Uf, bf, Wc, Uc, bc, Wo, Uo, bo);
    mdhp_kernel<<<BB, 512>>>(alpha, beta, theta, tspan, A, Bm, C);
    prep_state<<<(BB * HH + 255) / 256, 256>>>(h0);
    xsplit<<<(SS * BB * DD / 4) / 256, 256>>>(x);
    xw_mma<<<dim3(GG / 128, (SS * BB) / 128), 512, XSMEM>>>();
    lstm_persist<<<dim3(32, 4), 512, SMEM>>>(c0, out);
    finalize<<<(BH + 255) / 256, 256>>>(out);
}

// round 11
// speedup vs baseline: 1.0078x; 1.0078x over previous
#include <cuda_runtime.h>
#include <cuda_bf16.h>
#include <math.h>
#include <stdint.h>

// Problem dimensions (fixed by the dataset)
#define SS 512   // timesteps
#define BB 128   // batch
#define DD 256   // input dim
#define HH 512   // hidden
#define GG 2048  // 4*H (gate-interleaved: col n = j*4 + gate)
#define BH (BB*HH)

// Device scratch (no runtime allocation allowed)
__device__ float g_bias[GG];                 // interleaved bias [2048]
__device__ __nv_bfloat16 g_UThi[GG*HH];      // U'^T hi  [2048 n][512 k] bf16
__device__ __nv_bfloat16 g_UTlo[GG*HH];      // U'^T lo
__device__ __nv_bfloat16 g_WThi[GG*DD];      // W'^T hi  [2048 n][256 k] bf16
__device__ __nv_bfloat16 g_WTlo[GG*DD];      // W'^T lo
__device__ __nv_bfloat16 g_xhi[(size_t)SS*BB*DD];  // x hi  [65536 m][256 k] bf16
__device__ __nv_bfloat16 g_xlo[(size_t)SS*BB*DD];  // x lo
__device__ __nv_bfloat16 g_hBhi[2*BB*HH];    // double-buffered h hi [2][128 b][512 k]
__device__ __nv_bfloat16 g_hBlo[2*BB*HH];    // double-buffered h lo
__device__ float g_mdhp[BH];                 // tanh(alpha@A - (beta*ts)@B + theta@C)
__device__ float g_c[BH];                    // final cell state (for finalize)
__device__ float g_xw[(size_t)SS*BB*GG];     // precomputed x@W' + b  (512 MB)
__device__ unsigned g_ctr4[4];               // per-rowgroup barrier counters

// ---------------------------------------------------------------------------
// helpers
// ---------------------------------------------------------------------------
__device__ __forceinline__ void mma_bf16(float* c, uint32_t a0, uint32_t a1,
                                         uint32_t a2, uint32_t a3,
                                         uint32_t b0, uint32_t b1) {
    asm volatile("mma.sync.aligned.m16n8k16.row.col.f32.bf16.bf16.f32 "
        "{%0,%1,%2,%3}, {%4,%5,%6,%7}, {%8,%9}, {%0,%1,%2,%3};"
        : "+f"(c[0]), "+f"(c[1]), "+f"(c[2]), "+f"(c[3])
        : "r"(a0), "r"(a1), "r"(a2), "r"(a3), "r"(b0), "r"(b1));
}
__device__ __forceinline__ void ldsm_x4(uint32_t* r, uint32_t addr) {
    asm volatile("ldmatrix.sync.aligned.m8n8.x4.shared.b16 {%0,%1,%2,%3}, [%4];"
        : "=r"(r[0]), "=r"(r[1]), "=r"(r[2]), "=r"(r[3]) : "r"(addr));
}
__device__ __forceinline__ void ldsm_x2(uint32_t& r0, uint32_t& r1, uint32_t addr) {
    asm volatile("ldmatrix.sync.aligned.m8n8.x2.shared.b16 {%0,%1}, [%2];"
        : "=r"(r0), "=r"(r1) : "r"(addr));
}
__device__ __forceinline__ uint32_t smem_cast(const void* p) {
    return (uint32_t)__cvta_generic_to_shared(p);
}

// ---------------------------------------------------------------------------
// Build bf16-split U'^T, W'^T (both [n][k], n gate-interleaved), and bias.
// ---------------------------------------------------------------------------
__global__ void prep_weights(const float* __restrict__ Wi, const float* __restrict__ Ui, const float* __restrict__ bi,
                             const float* __restrict__ Wf, const float* __restrict__ Uf, const float* __restrict__ bf,
                             const float* __restrict__ Wc, const float* __restrict__ Uc, const float* __restrict__ bc,
                             const float* __restrict__ Wo, const float* __restrict__ Uo, const float* __restrict__ bo)
{
    int idx = blockIdx.x * blockDim.x + threadIdx.x;
    int stride = gridDim.x * blockDim.x;
    for (int i = idx; i < HH * GG; i += stride) {
        {   // U'^T bf16 hi/lo: i = n*512 + k
            int n = i >> 9, k = i & 511;
            int j = n >> 2, g = n & 3;
            const float* U = (g == 0) ? Ui : (g == 1) ? Uf : (g == 2) ? Uc : Uo;
            float u = U[k * HH + j];
            __nv_bfloat16 hi = __float2bfloat16(u);
            g_UThi[i] = hi;
            g_UTlo[i] = __float2bfloat16(u - __bfloat162float(hi));
        }
        if (i < GG * DD) {   // W'^T bf16 hi/lo: i = n*256 + k
            int n = i >> 8, k = i & 255;
            int j = n >> 2, g = n & 3;
            const float* W = (g == 0) ? Wi : (g == 1) ? Wf : (g == 2) ? Wc : Wo;
            float w = W[k * HH + j];
            __nv_bfloat16 hi = __float2bfloat16(w);
            g_WThi[i] = hi;
            g_WTlo[i] = __float2bfloat16(w - __bfloat162float(hi));
        }
        if (i < GG) {
            int j = i >> 2, g = i & 3;
            const float* bptr = (g == 0) ? bi : (g == 1) ? bf : (g == 2) ? bc : bo;
            g_bias[i] = bptr[j];
        }
    }
}

// split x into bf16 hi/lo (16.7M elements, 4 per thread)
__global__ void xsplit(const float* __restrict__ x)
{
    size_t i = (size_t)blockIdx.x * blockDim.x + threadIdx.x;   // float4 index
    float4 v = *((const float4*)x + i);
    __nv_bfloat16 h0 = __float2bfloat16(v.x);
    __nv_bfloat16 h1 = __float2bfloat16(v.y);
    __nv_bfloat16 h2 = __float2bfloat16(v.z);
    __nv_bfloat16 h3 = __float2bfloat16(v.w);
    __nv_bfloat16 l0 = __float2bfloat16(v.x - __bfloat162float(h0));
    __nv_bfloat16 l1 = __float2bfloat16(v.y - __bfloat162float(h1));
    __nv_bfloat16 l2 = __float2bfloat16(v.z - __bfloat162float(h2));
    __nv_bfloat16 l3 = __float2bfloat16(v.w - __bfloat162float(h3));
    ushort4 ph = make_ushort4(__bfloat16_as_ushort(h0), __bfloat16_as_ushort(h1),
                              __bfloat16_as_ushort(h2), __bfloat16_as_ushort(h3));
    ushort4 pl = make_ushort4(__bfloat16_as_ushort(l0), __bfloat16_as_ushort(l1),
                              __bfloat16_as_ushort(l2), __bfloat16_as_ushort(l3));
    *((ushort4*)g_xhi + i) = ph;
    *((ushort4*)g_xlo + i) = pl;
}

// ---------------------------------------------------------------------------
// mdhp = tanh(alpha @ A - (beta*tspan) @ B + theta @ C)   [B,H]
// ---------------------------------------------------------------------------
__global__ void mdhp_kernel(const float* __restrict__ alpha, const float* __restrict__ beta,
                            const float* __restrict__ theta, const float* __restrict__ tspan,
                            const float* __restrict__ A, const float* __restrict__ Bm,
                            const float* __restrict__ C)
{
    int b = blockIdx.x;
    int j = threadIdx.x;   // 0..511
    __shared__ float sa[256], sb[256], st[16];
    float ts = tspan[b];
    if (j < 256) {
        sa[j] = alpha[b * 256 + j];
        sb[j] = beta[b * 256 + j] * ts;
    }
    if (j < 16) st[j] = theta[b * 16 + j];
    __syncthreads();
    float acc = 0.f;
    #pragma unroll 4
    for (int k = 0; k < 256; k++)
        acc += sa[k] * A[k * 512 + j] - sb[k] * Bm[k * 512 + j];
    #pragma unroll
    for (int k = 0; k < 16; k++)
        acc += st[k] * C[k * 512 + j];
    g_mdhp[b * 512 + j] = tanhf(acc);
}

// zero barrier counters + bf16-split h0 into g_hB buffer 0
__global__ void prep_state(const float* __restrict__ h0)
{
    int i = blockIdx.x * blockDim.x + threadIdx.x;
    if (i < 4) g_ctr4[i] = 0u;
    if (i < BB * HH) {
        float v = h0[i];                       // i = b*512 + k
        __nv_bfloat16 hi = __float2bfloat16(v);
        g_hBhi[i] = hi;
        g_hBlo[i] = __float2bfloat16(v - __bfloat162float(hi));
    }
}

// ---------------------------------------------------------------------------
// xW GEMM on mma.sync bf16 (2-way split, 3-term product) with ldmatrix:
//   g_xw[65536, 2048] = x[65536, 256] @ W'[256, 2048] + bias
// Block: 128x128 C tile, 256 threads = 8 warps (4 M x 2 N), warp tile 32x64.
// K in 4 chunks of 64; smem rows padded to 36 words (stride 4 mod 32 banks).
// ---------------------------------------------------------------------------
#define ROWX 36   // uint32 words per padded row (32 data words = 64 bf16)
__global__ __launch_bounds__(256, 2) void xw_mma()
{
    extern __shared__ __align__(16) uint32_t xs[];
    uint32_t* a_hi = xs;                    // [128][36]
    uint32_t* a_lo = xs + 128 * ROWX;
    uint32_t* b_hi = xs + 2 * 128 * ROWX;
    uint32_t* b_lo = xs + 3 * 128 * ROWX;

    const int tid  = threadIdx.x;
    const int lane = tid & 31;
    const int wid  = tid >> 5;
    const int mbase = (wid & 3) * 32;       // 0,32,64,96
    const int nbase = (wid >> 2) * 64;      // 0,64
    const int r  = lane >> 2;               // 0..7
    const int tq = lane & 3;                // 0..3
    const int n0 = blockIdx.x * 128;
    const int m0 = blockIdx.y * 128;

    // ldmatrix per-lane base addresses (bytes)
    const uint32_t aRowOff = ((mbase + (lane & 15)) * ROWX + (lane >> 4) * 4) << 2;
    const uint32_t aHiB = smem_cast(a_hi) + aRowOff;
    const uint32_t aLoB = smem_cast(a_lo) + aRowOff;
    const uint32_t bRowOff = ((nbase + (lane & 7)) * ROWX + ((lane >> 3) & 1) * 4) << 2;
    const uint32_t bHiB = smem_cast(b_hi) + bRowOff;
    const uint32_t bLoB = smem_cast(b_lo) + bRowOff;
    const uint32_t FSTRIDE = (16 * ROWX) << 2;   // f: +16 rows
    const uint32_t JSTRIDE = (8 * ROWX) << 2;    // j: +8 rows

    float c[2][8][4];
    #pragma unroll
    for (int f = 0; f < 2; f++)
        #pragma unroll
        for (int j = 0; j < 8; j++)
            #pragma unroll
            for (int q = 0; q < 4; q++) c[f][j][q] = 0.f;

    for (int kc = 0; kc < 4; kc++) {
        const int k0 = kc * 64;
        // load A/B 64-k chunks (bf16 hi/lo), 8 uint4 per row
        #pragma unroll
        for (int q = 0; q < 4; q++) {
            int u = tid + q * 256;          // 0..1023
            int row = u >> 3;               // 0..127
            int c4  = u & 7;                // uint4 within row
            uint4 vah = *((const uint4*)(g_xhi + (size_t)(m0 + row) * DD + k0) + c4);
            uint4 val = *((const uint4*)(g_xlo + (size_t)(m0 + row) * DD + k0) + c4);
            uint4 vbh = *((const uint4*)(g_WThi + (size_t)(n0 + row) * DD + k0) + c4);
            uint4 vbl = *((const uint4*)(g_WTlo + (size_t)(n0 + row) * DD + k0) + c4);
            *(uint4*)(a_hi + row * ROWX + c4 * 4) = vah;
            *(uint4*)(a_lo + row * ROWX + c4 * 4) = val;
            *(uint4*)(b_hi + row * ROWX + c4 * 4) = vbh;
            *(uint4*)(b_lo + row * ROWX + c4 * 4) = vbl;
        }
        __syncthreads();

        #pragma unroll
        for (int ks = 0; ks < 4; ks++) {
            const uint32_t ksOff = ks * 32;          // 8 words
            uint32_t ah[2][4], al[2][4];
            ldsm_x4(ah[0], aHiB + ksOff);
            ldsm_x4(ah[1], aHiB + FSTRIDE + ksOff);
            ldsm_x4(al[0], aLoB + ksOff);
            ldsm_x4(al[1], aLoB + FSTRIDE + ksOff);
            #pragma unroll
            for (int j = 0; j < 8; j++) {
                uint32_t bh0, bh1, bl0, bl1;
                ldsm_x2(bh0, bh1, bHiB + j * JSTRIDE + ksOff);
                ldsm_x2(bl0, bl1, bLoB + j * JSTRIDE + ksOff);
                #pragma unroll
                for (int f = 0; f < 2; f++) {
                    mma_bf16(c[f][j], ah[f][0], ah[f][1], ah[f][2], ah[f][3], bh0, bh1);
                    mma_bf16(c[f][j], ah[f][0], ah[f][1], ah[f][2], ah[f][3], bl0, bl1);
                    mma_bf16(c[f][j], al[f][0], al[f][1], al[f][2], al[f][3], bh0, bh1);
                }
            }
        }
        __syncthreads();
    }

    // epilogue (streaming stores: keep 512MB of g_xw out of L2's way)
    #pragma unroll
    for (int f = 0; f < 2; f++) {
        int row0 = m0 + mbase + f * 16 + r;
        #pragma unroll
        for (int j = 0; j < 8; j++) {
            int col = n0 + nbase + j * 8 + 2 * tq;
            float2 bb = *(const float2*)&g_bias[col];
            float2 o0 = make_float2(c[f][j][0] + bb.x, c[f][j][1] + bb.y);
            float2 o1 = make_float2(c[f][j][2] + bb.x, c[f][j][3] + bb.y);
            __stcs((float2*)&g_xw[(size_t)row0 * GG + col], o0);
            __stcs((float2*)&g_xw[(size_t)(row0 + 8) * GG + col], o1);
        }
    }
}

// ---------------------------------------------------------------------------
// Persistent LSTM recurrence on mma.sync bf16 (r8 structure, ldmatrix loads).
// ---------------------------------------------------------------------------
#define ROWW 260   // uint32 words per padded bf16 row (520 bf16; 256 data words)
__global__ __launch_bounds__(512) void lstm_persist(const float* __restrict__ c0,
                                                    float* __restrict__ out)
{
    extern __shared__ __align__(16) uint32_t smw[];
    uint32_t* u_hi = smw;                               // [64][260]
    uint32_t* u_lo = smw + 64 * ROWW;                   // [64][260]
    uint32_t* h_hi = smw + 2 * 64 * ROWW;               // [32][260]
    uint32_t* h_lo = smw + 2 * 64 * ROWW + 32 * ROWW;   // [32][260]
    float*    part = (float*)(smw + 2 * 64 * ROWW + 2 * 32 * ROWW); // [2][32][68]

    const int tid = threadIdx.x;
    const int bx  = blockIdx.x;            // 0..31 col block
    const int rg  = blockIdx.y;            // 0..3  row group
    const int n0  = bx * 64;               // interleaved gate-col base
    const int b0  = rg * 32;               // batch row base

    const int lane = tid & 31;
    const int wid  = tid >> 5;             // 0..15
    const int kseg  = wid >> 3;            // 0..1  K half
    const int ow    = wid & 7;             // 0..7  output warp
    const int mbase = (ow >> 2) * 16;      // 0 or 16
    const int nbase = (ow & 3) * 16;       // 0,16,32,48
    const int r  = lane >> 2;              // 0..7
    const int tq = lane & 3;               // 0..3

    const int pr = tid >> 4;               // 0..31
    const int pj = tid & 15;               // 0..15
    const int jglob = bx * 16 + pj;
    const int pidx = (b0 + pr) * HH + jglob;

    // ldmatrix per-lane base addresses (bytes); kseg offset folded in
    const uint32_t ksegOff = (kseg * 128) << 2;
    const uint32_t aRowOff = ((mbase + (lane & 15)) * ROWW + (lane >> 4) * 4) << 2;
    const uint32_t hHiB = smem_cast(h_hi) + aRowOff + ksegOff;
    const uint32_t hLoB = smem_cast(h_lo) + aRowOff + ksegOff;
    const uint32_t bRowOff = ((nbase + (lane & 7)) * ROWW + ((lane >> 3) & 1) * 4) << 2;
    const uint32_t uHiB = smem_cast(u_hi) + bRowOff + ksegOff;
    const uint32_t uLoB = smem_cast(u_lo) + bRowOff + ksegOff;
    const uint32_t JSTR = (8 * ROWW) << 2;

    // ---- load persistent U'^T slice (bf16 hi/lo) ----
    #pragma unroll
    for (int q = 0; q < 8; q++) {
        int u = tid + q * 512;              // 0..4095
        int row = u >> 6;                   // 0..63
        int c4  = u & 63;
        uint4 vh = *((const uint4*)(g_UThi + (size_t)(n0 + row) * HH) + c4);
        uint4 vl = *((const uint4*)(g_UTlo + (size_t)(n0 + row) * HH) + c4);
        *(uint4*)(u_hi + row * ROWW + c4 * 4) = vh;
        *(uint4*)(u_lo + row * ROWW + c4 * 4) = vl;
    }

    float cr = c0[pidx];
    float mr = g_mdhp[pidx];
    __syncthreads();

    for (int t = 0; t < SS; t++) {
        const __nv_bfloat16* hbh = g_hBhi + (size_t)(t & 1) * (BB * HH);
        const __nv_bfloat16* hbl = g_hBlo + (size_t)(t & 1) * (BB * HH);
        #pragma unroll
        for (int q = 0; q < 4; q++) {
            int u = tid + q * 512;          // 0..2047
            int row = u >> 6;               // 0..31
            int c4  = u & 63;
            uint4 vh = __ldcg((const uint4*)(hbh + (size_t)(b0 + row) * HH) + c4);
            uint4 vl = __ldcg((const uint4*)(hbl + (size_t)(b0 + row) * HH) + c4);
            *(uint4*)(h_hi + row * ROWW + c4 * 4) = vh;
            *(uint4*)(h_lo + row * ROWW + c4 * 4) = vl;
        }
        float4 xw4 = __ldcs((const float4*)&g_xw[((size_t)t * BB + b0 + pr) * GG + n0 + pj * 4]);
        __syncthreads();

        float c[2][4] = {};
        #pragma unroll 4
        for (int ks = 0; ks < 16; ks++) {
            const uint32_t ksOff = ks * 32;
            uint32_t ah[4], al[4];
            ldsm_x4(ah, hHiB + ksOff);
            ldsm_x4(al, hLoB + ksOff);
            #pragma unroll
            for (int j = 0; j < 2; j++) {
                uint32_t bh0, bh1, bl0, bl1;
                ldsm_x2(bh0, bh1, uHiB + j * JSTR + ksOff);
                ldsm_x2(bl0, bl1, uLoB + j * JSTR + ksOff);
                mma_bf16(c[j], ah[0], ah[1], ah[2], ah[3], bh0, bh1);
                mma_bf16(c[j], ah[0], ah[1], ah[2], ah[3], bl0, bl1);
                mma_bf16(c[j], al[0], al[1], al[2], al[3], bh0, bh1);
            }
        }

        #pragma unroll
        for (int j = 0; j < 2; j++) {
            float* p = part + kseg * (32 * 68) + (mbase + r) * 68 + nbase + j * 8 + 2 * tq;
            *(float2*)p            = make_float2(c[j][0], c[j][1]);
            *(float2*)(p + 8 * 68) = make_float2(c[j][2], c[j][3]);
        }
        __syncthreads();

        {
            float4 p0 = *(const float4*)&part[pr * 68 + pj * 4];
            float4 p1 = *(const float4*)&part[32 * 68 + pr * 68 + pj * 4];
            float gi = p0.x + p1.x + xw4.x;
            float gf = p0.y + p1.y + xw4.y;
            float gc = p0.z + p1.z + xw4.z;
            float go = p0.w + p1.w + xw4.w;
            float it_ = 1.f / (1.f + __expf(-gi));
            float ft  = 1.f / (1.f + __expf(-gf));
            float ch  = tanhf(gc);
            float ot  = 1.f / (1.f + __expf(-go));
            float cn  = mr * (ft * cr + it_ * ch);
            cr = cn;
            float hn = ot * tanhf(cn);
            out[(size_t)t * BH + pidx] = hn;
            size_t nb = (size_t)((t + 1) & 1) * (BB * HH);
            __nv_bfloat16 hb = __float2bfloat16(hn);
            g_hBhi[nb + pidx] = hb;
            g_hBlo[nb + pidx] = __float2bfloat16(hn - __bfloat162float(hb));
        }

        __syncthreads();
        if (tid == 0) {
            __threadfence();
            atomicAdd(&g_ctr4[rg], 1u);
            unsigned target = (unsigned)(t + 1) * 32u;
            while (*(volatile unsigned*)&g_ctr4[rg] < target) { }
            __threadfence();
        }
        __syncthreads();
    }

    g_c[pidx] = cr;
}

// copy h_T (== outputs[S-1]) and c_T into the output tail
__global__ void finalize(float* __restrict__ out)
{
    int i = blockIdx.x * blockDim.x + threadIdx.x;
    if (i < BH) {
        out[(size_t)SS * BH + i]      = out[(size_t)(SS - 1) * BH + i];
        out[(size_t)SS * BH + BH + i] = g_c[i];
    }
}

// ---------------------------------------------------------------------------
extern "C" void kernel_launch(void* const* d_in, const int* in_sizes, int n_in,
                              void* d_out, int out_size)
{
    const float* x     = (const float*)d_in[0];
    const float* h0    = (const float*)d_in[1];
    const float* c0    = (const float*)d_in[2];
    const float* alpha = (const float*)d_in[3];
    const float* beta  = (const float*)d_in[4];
    const float* theta = (const float*)d_in[5];
    const float* tspan = (const float*)d_in[6];
    const float* A     = (const float*)d_in[7];
    const float* Bm    = (const float*)d_in[8];
    const float* C     = (const float*)d_in[9];
    const float* Wi = (const float*)d_in[10];
    const float* Ui = (const float*)d_in[11];
    const float* bi = (const float*)d_in[12];
    const float* Wf = (const float*)d_in[13];
    const float* Uf = (const float*)d_in[14];
    const float* bf = (const float*)d_in[15];
    const float* Wc = (const float*)d_in[16];
    const float* Uc = (const float*)d_in[17];
    const float* bc = (const float*)d_in[18];
    const float* Wo = (const float*)d_in[19];
    const float* Uo = (const float*)d_in[20];
    const float* bo = (const float*)d_in[21];
    float* out = (float*)d_out;

    const int SMEM  = (2 * 64 * ROWW + 2 * 32 * ROWW + 2 * 32 * 68) * 4;  // 217088 B
    const int XSMEM = 4 * 128 * ROWX * 4;                                  // 73728 B
    cudaFuncSetAttribute(lstm_persist, cudaFuncAttributeMaxDynamicSharedMemorySize, SMEM);
    cudaFuncSetAttribute(xw_mma, cudaFuncAttributeMaxDynamicSharedMemorySize, XSMEM);

    // order chosen so the ncu capture window lands on xw_mma
    prep_weights<<<1024, 256>>>(Wi, Ui, bi, Wf, Uf, bf, Wc, Uc, bc, Wo, Uo, bo);
    mdhp_kernel<<<BB, 512>>>(alpha, beta, theta, tspan, A, Bm, C);
    xsplit<<<(SS * BB * DD / 4) / 256, 256>>>(x);
    xw_mma<<<dim3(GG / 128, (SS * BB) / 128), 256, XSMEM>>>();
    prep_state<<<(BB * HH + 255) / 256, 256>>>(h0);
    lstm_persist<<<dim3(32, 4), 512, SMEM>>>(c0, out);
    finalize<<<(BH + 255) / 256, 256>>>(out);
}